// round 13
// baseline (speedup 1.0000x reference)
#include <cuda_runtime.h>
#include <cuda_fp16.h>
#include <cstdint>

#define BQ 4096
#define ZD 512
#define HD 384
#define KD2 768
#define KC 64

// ---------------- device state ----------------
__device__ float g_z[2][(size_t)BQ * ZD];
__device__ float g_h[2][(size_t)BQ * HD];
__device__ __half g_zh[2][(size_t)BQ * ZD];
__device__ __half g_hh[2][(size_t)BQ * HD];
__device__ __half g_ah[(size_t)BQ * HD];
__device__ __half g_w1[(size_t)HD * ZD];
__device__ __half g_w2[(size_t)ZD * KD2];
__device__ __half g_w3[(size_t)HD * KD2];

// ---------------- helpers ----------------
__device__ __forceinline__ uint32_t smem_to_u32(const void* p) {
    uint32_t a;
    asm("{ .reg .u64 t; cvta.to.shared.u64 t, %1; cvt.u32.u64 %0, t; }" : "=r"(a) : "l"(p));
    return a;
}
__device__ __forceinline__ float lrelu(float x) { return x > 0.f ? x : 0.01f * x; }
__device__ __forceinline__ uint32_t pack_h2(float a, float b) {
    __half2 p = __floats2half2_rn(a, b);
    return *(uint32_t*)&p;
}
__device__ __forceinline__ uint32_t swz128(uint32_t row, uint32_t c) {
    return row * 128u + ((c ^ (row & 7u)) << 4);
}

#define CP_ASYNC16(dst, src) \
    asm volatile("cp.async.cg.shared.global [%0], [%1], 16;" \
                 :: "r"(dst), "l"((unsigned long long)__cvta_generic_to_global(src)) : "memory")
#define CP_COMMIT() asm volatile("cp.async.commit_group;" ::: "memory")

#define LDSM_X4(r0, r1, r2, r3, addr) \
    asm volatile("ldmatrix.sync.aligned.m8n8.x4.shared.b16 {%0,%1,%2,%3}, [%4];" \
                 : "=r"(r0), "=r"(r1), "=r"(r2), "=r"(r3) : "r"(addr))

#define MMA_F16(c, a, b) \
    asm volatile("mma.sync.aligned.m16n8k16.row.col.f32.f16.f16.f32 " \
                 "{%0,%1,%2,%3}, {%4,%5,%6,%7}, {%8,%9}, {%0,%1,%2,%3};" \
                 : "+f"((c)[0]), "+f"((c)[1]), "+f"((c)[2]), "+f"((c)[3]) \
                 : "r"((a)[0]), "r"((a)[1]), "r"((a)[2]), "r"((a)[3]), \
                   "r"((b)[0]), "r"((b)[1]))

// ---------------- prep / init ----------------
__global__ void prep_weights(const float* __restrict__ W1, const float* __restrict__ W2,
                             const float* __restrict__ W3)
{
    int i = blockIdx.x * 256 + threadIdx.x;
    const int s1 = HD * ZD, s2 = ZD * KD2, s3 = HD * KD2;
    if (i < s1) g_w1[i] = __float2half_rn(W1[i]);
    else if (i < s1 + s2) { int j = i - s1; g_w2[j] = __float2half_rn(W2[j]); }
    else if (i < s1 + s2 + s3) { int j = i - s1 - s2; g_w3[j] = __float2half_rn(W3[j]); }
}

__global__ void init_kernel(const float* __restrict__ z, const float* __restrict__ hin,
                            float* __restrict__ out, int T)
{
    int idx = blockIdx.x * blockDim.x + threadIdx.x;
    if (idx < BQ * ZD) {
        float v = z[idx];
        g_z[0][idx] = v;
        g_zh[0][idx] = __float2half_rn(v);
        int m = idx >> 9, n = idx & (ZD - 1);
        out[((size_t)m * T) * ZD + n] = 0.f;
    }
    if (idx < BQ * HD) {
        float v = hin[idx];
        g_h[0][idx] = v;
        g_hh[0][idx] = __float2half_rn(v);
    }
}

// ---------------- tensor-core GEMM (mma.sync fp16) ----------------
// Tile TM(M) x 128(N), 128 threads (4 warps 2x2), warp tile (TM/2)x64,
// KC=64 chunks (128B rows, XOR swizzle), 2-stage double buffer with the
// PROVEN ordering (wait -> syncthreads -> issue -> compute), plus
// register-level fragment double buffering inside the kk loop.
template <int TM, int KIND>
__global__ __launch_bounds__(128, 4)
void rec_gemm(int parity, int t, float r,
              const float* __restrict__ b1, const float* __restrict__ b2,
              const float* __restrict__ b3, const float* __restrict__ z0,
              float* __restrict__ out, int T)
{
    constexpr int MF = TM / 32;
    constexpr int A_TILE_B = TM * 128;
    constexpr int B_TILE_B = 128 * 128;
    constexpr int OFF_A = 0;
    constexpr int OFF_B = A_TILE_B;
    constexpr int STAGE_B = A_TILE_B + B_TILE_B;
    constexpr int NA = TM * 8;
    constexpr int NVEC = (NA + 1024) / 128;
    constexpr int AS = (KIND == 0) ? ZD : HD;
    constexpr int NCH = (KIND == 0) ? (ZD / KC) : (KD2 / KC);

    extern __shared__ char smem[];
    const uint32_t sb = smem_to_u32(smem);
    const int tid = threadIdx.x;
    const int wid = tid >> 5, lane = tid & 31;
    const int wm = (wid >> 1) * (TM / 2);
    const int wn = (wid & 1) * 64;
    const int n0 = blockIdx.x * 128;
    const int row0 = blockIdx.y * TM;
    const bool is_z = (n0 < ZD);

    const __half* B;
    int bs;
    if (KIND == 0)  { B = g_w1 + (size_t)n0 * ZD;         bs = ZD; }
    else if (is_z)  { B = g_w2 + (size_t)n0 * KD2;        bs = KD2; }
    else            { B = g_w3 + (size_t)(n0 - ZD) * KD2; bs = KD2; }

    float acc[MF][8][4];
#pragma unroll
    for (int i = 0; i < MF; i++)
#pragma unroll
        for (int j = 0; j < 8; j++)
#pragma unroll
            for (int k = 0; k < 4; k++) acc[i][j][k] = 0.f;

    const int a_row = wm + (lane & 7) + ((lane >> 3) & 1) * 8;
    const uint32_t a_cbit = (uint32_t)(lane >> 4);
    const int b_row = wn + (lane & 7) + (lane >> 4) * 8;
    const uint32_t b_cbit = (uint32_t)((lane >> 3) & 1);
    const uint32_t lx = (uint32_t)(lane & 7);

    auto issue = [&](int c) {
        const int kc = c * KC;
        const __half* A;
        int kA;
        if (KIND == 0) { A = g_zh[parity] + (size_t)row0 * ZD; kA = kc; }
        else if (kc < HD) { A = g_ah + (size_t)row0 * HD; kA = kc; }
        else { A = g_hh[parity] + (size_t)row0 * HD; kA = kc - HD; }
        const uint32_t stg = sb + (uint32_t)(c & 1) * STAGE_B;
#pragma unroll
        for (int i = 0; i < NVEC; i++) {
            int g = i * 128 + tid;
            uint32_t dst;
            const __half* srcp;
            if (g < NA) {
                uint32_t row = g >> 3, c8 = g & 7;
                dst = stg + OFF_A + swz128(row, c8);
                srcp = A + (size_t)row * AS + kA + c8 * 8;
            } else {
                int j = g - NA;
                uint32_t row = j >> 3, c8 = j & 7;
                dst = stg + OFF_B + swz128(row, c8);
                srcp = B + (size_t)row * bs + kc + c8 * 8;
            }
            CP_ASYNC16(dst, srcp);
        }
        CP_COMMIT();
    };

    issue(0);
    for (int c = 0; c < NCH; c++) {
        // PROVEN ordering: own-groups wait, then barrier publishes ALL threads'
        // cp.async results; barrier also proves compute(c-1) finished so the
        // other stage buffer is reusable.
        asm volatile("cp.async.wait_group 0;" ::: "memory");
        __syncthreads();

        const uint32_t stg = sb + (uint32_t)(c & 1) * STAGE_B;
        uint32_t Af[MF][4], Bf[2][8][2];

        // Preload kk=0 fragments BEFORE issuing next chunk's copies, so the
        // LDSM latency hides behind the cp.async issue burst below.
#pragma unroll
        for (int nb = 0; nb < 4; nb++) {
            uint32_t bd = stg + OFF_B + (uint32_t)(b_row + nb * 16) * 128u + ((b_cbit ^ lx) << 4);
            LDSM_X4(Bf[0][nb * 2][0], Bf[0][nb * 2][1], Bf[0][nb * 2 + 1][0], Bf[0][nb * 2 + 1][1], bd);
        }
#pragma unroll
        for (int mf = 0; mf < MF; mf++) {
            uint32_t ad = stg + OFF_A + (uint32_t)(a_row + mf * 16) * 128u + ((a_cbit ^ lx) << 4);
            LDSM_X4(Af[mf][0], Af[mf][1], Af[mf][2], Af[mf][3], ad);
        }

        if (c + 1 < NCH) issue(c + 1);

#pragma unroll
        for (int kk = 0; kk < 4; kk++) {
            // prefetch B(kk+1) before this kk's MMAs (latency behind MMA issue)
            if (kk < 3) {
                const uint32_t bc = (uint32_t)((kk + 1) * 2) + b_cbit;
#pragma unroll
                for (int nb = 0; nb < 4; nb++) {
                    uint32_t bd = stg + OFF_B + (uint32_t)(b_row + nb * 16) * 128u + ((bc ^ lx) << 4);
                    LDSM_X4(Bf[(kk + 1) & 1][nb * 2][0], Bf[(kk + 1) & 1][nb * 2][1],
                            Bf[(kk + 1) & 1][nb * 2 + 1][0], Bf[(kk + 1) & 1][nb * 2 + 1][1], bd);
                }
            }
#pragma unroll
            for (int mf = 0; mf < MF; mf++)
#pragma unroll
                for (int nf = 0; nf < 8; nf++) MMA_F16(acc[mf][nf], Af[mf], Bf[kk & 1][nf]);
            // reload A for kk+1 after its consumers issued (ptxas handles WAR)
            if (kk < 3) {
                const uint32_t ac = (uint32_t)((kk + 1) * 2) + a_cbit;
#pragma unroll
                for (int mf = 0; mf < MF; mf++) {
                    uint32_t ad = stg + OFF_A + (uint32_t)(a_row + mf * 16) * 128u + ((ac ^ lx) << 4);
                    LDSM_X4(Af[mf][0], Af[mf][1], Af[mf][2], Af[mf][3], ad);
                }
            }
        }
    }

    // ---------------- epilogue ----------------
    const int quad = lane >> 2, tq = (lane & 3) * 2;
#pragma unroll
    for (int mf = 0; mf < MF; mf++) {
        const int rb = row0 + wm + mf * 16 + quad;
#pragma unroll
        for (int nf = 0; nf < 8; nf++) {
            const int n = n0 + wn + nf * 8 + tq;
#pragma unroll
            for (int half = 0; half < 2; half++) {
                const int m = rb + half * 8;
                const float c0 = acc[mf][nf][half * 2 + 0];
                const float c1 = acc[mf][nf][half * 2 + 1];
                if (KIND == 0) {
                    float v0 = lrelu(c0 + b1[n]);
                    float v1 = lrelu(c1 + b1[n + 1]);
                    *(uint32_t*)(g_ah + (size_t)m * HD + n) = pack_h2(v0, v1);
                } else if (is_z) {
                    float2 zv = *(const float2*)(g_z[parity] + (size_t)m * ZD + n);
                    float2 ov = *(const float2*)(z0 + (size_t)m * ZD + n);
                    float v0 = lrelu(c0 + b2[n]) * r + zv.x;
                    float v1 = lrelu(c1 + b2[n + 1]) * r + zv.y;
                    *(float2*)(g_z[parity ^ 1] + (size_t)m * ZD + n) = make_float2(v0, v1);
                    *(float2*)(out + ((size_t)m * T + t) * ZD + n) = make_float2(v0 - ov.x, v1 - ov.y);
                    *(uint32_t*)(g_zh[parity ^ 1] + (size_t)m * ZD + n) = pack_h2(v0, v1);
                } else {
                    const int nh = n - ZD;
                    float2 hv = *(const float2*)(g_h[parity] + (size_t)m * HD + nh);
                    float v0 = lrelu(c0 + b3[nh]) * r + hv.x;
                    float v1 = lrelu(c1 + b3[nh + 1]) * r + hv.y;
                    *(float2*)(g_h[parity ^ 1] + (size_t)m * HD + nh) = make_float2(v0, v1);
                    *(uint32_t*)(g_hh[parity ^ 1] + (size_t)m * HD + nh) = pack_h2(v0, v1);
                }
            }
        }
    }
}

// ---------------- host ----------------
extern "C" void kernel_launch(void* const* d_in, const int* in_sizes, int n_in,
                              void* d_out, int out_size)
{
    const float* z  = (const float*)d_in[0];
    const float* h0 = (const float*)d_in[1];
    const float* W1 = (const float*)d_in[2];
    const float* b1 = (const float*)d_in[3];
    const float* W2 = (const float*)d_in[4];
    const float* b2 = (const float*)d_in[5];
    const float* W3 = (const float*)d_in[6];
    const float* b3 = (const float*)d_in[7];
    float* out = (float*)d_out;

    const int T = out_size / (BQ * ZD);
    const float r = 0.2f * 4.0f / (float)T;

    const int SM64 = 2 * (64 * 128 + 128 * 128);   // 49152
    const int SM32 = 2 * (32 * 128 + 128 * 128);   // 40960
    cudaFuncSetAttribute((rec_gemm<64, 1>), cudaFuncAttributeMaxDynamicSharedMemorySize, SM64);
    cudaFuncSetAttribute((rec_gemm<32, 0>), cudaFuncAttributeMaxDynamicSharedMemorySize, SM32);

    const int wtot = HD * ZD + ZD * KD2 + HD * KD2;
    prep_weights<<<(wtot + 255) / 256, 256>>>(W1, W2, W3);
    init_kernel<<<(BQ * ZD + 255) / 256, 256>>>(z, h0, out, T);

    int parity = 0;
    for (int t = 1; t < T; t++) {
        rec_gemm<32, 0><<<dim3(HD / 128, BQ / 32), 128, SM32>>>(parity, t, r, b1, b2, b3, z, out, T);
        rec_gemm<64, 1><<<dim3((ZD + HD) / 128, BQ / 64), 128, SM64>>>(parity, t, r, b1, b2, b3, z, out, T);
        parity ^= 1;
    }
}